// round 13
// baseline (speedup 1.0000x reference)
#include <cuda_runtime.h>
#include <cuda_fp16.h>
#include <cstdint>

// Problem constants (fixed by the dataset)
#define NN 100000        // nodes
#define NE 3200000       // edges
#define DF 128           // input feat
#define NH1 128          // layer1 out
#define NH2 64           // layer2 out
#define NG 256           // graphs
#define NC 10            // classes

#define SCAN_B 1024
#define SCAN_NB ((NN + SCAN_B - 1) / SCAN_B)   // 98

// ---------------- scratch (static device memory; no allocation) -------------
// Invariants across calls: g_cnt == 0 on entry; g_blocksum == 0 on entry.
__device__ int   g_is64;               // 1 if indices are int64, 0 if int32
__device__ float g_dis[NN];            // deg^-1/2
__device__ int   g_cnt[NN];            // per-dst edge count
__device__ int   g_rowptr[NN + 1];     // CSR row pointers
__device__ int   g_woff[NN];           // scatter write offsets
__device__ int   g_blocksum[SCAN_NB];  // flagged block sums (value+1)
__device__ int   g_csr_src[NE];        // CSR column (src) indices
__device__ __align__(16) uint2 g_h1h[NN * 32];    // (x @ W1)*dis, fp16, 128 h/row
__device__ __align__(16) uint2 g_r1h[NN * 32];    // relu(gcn1), fp16
__device__ __align__(16) unsigned g_h2h[NN * 32]; // (r1 @ W2)*dis, fp16, 64 h/row
__device__ float g_pool[NG * NH2];     // graph sums
__device__ float g_pcnt[NG];           // graph node counts

// index load helper: p holds either int32 or int64 elements
__device__ __forceinline__ int ld_idx(const void* p, long long i, int is64) {
    if (is64) return (int)((const long long*)p)[i];
    return ((const int*)p)[i];
}

// ---------------- hist (+ dtype detect) ----------------------------------------

__global__ void k_hist(const void* __restrict__ ei) {
    __shared__ int nz;
    if (threadIdx.x == 0) nz = 0;
    __syncthreads();
    if (threadIdx.x < 256) {
        if (((const int*)ei)[2 * threadIdx.x + 1] != 0) atomicOr(&nz, 1);
    }
    __syncthreads();
    int is64 = (nz == 0);
    if (blockIdx.x == 0 && threadIdx.x == 0) g_is64 = is64;
    int e = blockIdx.x * blockDim.x + threadIdx.x;
    if (e < NE) {
        int d = ld_idx(ei, (long long)NE + e, is64);
        atomicAdd(&g_cnt[d], 1);
    }
}

// ---------------- single-pass scan (decoupled lookback) ------------------------
__global__ void k_scan() {
    __shared__ int s[SCAN_B];
    __shared__ int pre[SCAN_NB];
    int t = threadIdx.x, b = blockIdx.x;
    int i = b * SCAN_B + t;
    int v = 0;
    if (i < NN) {
        v = g_cnt[i];
        g_cnt[i] = 0;                       // re-establish invariant for next call
        g_dis[i] = rsqrtf((float)v + 1.0f);
    }
    s[t] = v;
    __syncthreads();
    #pragma unroll
    for (int off = 1; off < SCAN_B; off <<= 1) {
        int add = (t >= off) ? s[t - off] : 0;
        __syncthreads();
        s[t] += add;
        __syncthreads();
    }
    int incl = s[t];
    if (t == SCAN_B - 1) {
        __threadfence();
        atomicExch(&g_blocksum[b], incl + 1);
    }
    if (b == 0) {
        for (int j = t; j < NG * NH2; j += SCAN_B) g_pool[j] = 0.f;
        if (t < NG) g_pcnt[t] = 0.f;
    }
    if (t < b) {
        volatile int* bs = g_blocksum;
        int x;
        do { x = bs[t]; } while (x == 0);
        pre[t] = x - 1;
    }
    __syncthreads();
    __shared__ int prefix;
    if (t == 0) {
        int p = 0;
        for (int j = 0; j < b; j++) p += pre[j];
        prefix = p;
    }
    __syncthreads();
    if (i < NN) {
        int excl = prefix + incl - v;
        g_rowptr[i] = excl;
        g_woff[i] = excl;
    }
    if (i == 0) g_rowptr[NN] = NE;
}

// ---------------- scatter -------------------------------------------------------

__global__ void k_scatter(const void* __restrict__ ei) {
    if (blockIdx.x == 0 && threadIdx.x < SCAN_NB) g_blocksum[threadIdx.x] = 0;
    int e = blockIdx.x * blockDim.x + threadIdx.x;
    int is64 = g_is64;
    if (e < NE) {
        int s = ld_idx(ei, e, is64);
        int d = ld_idx(ei, (long long)NE + e, is64);
        int pos = atomicAdd(&g_woff[d], 1);
        g_csr_src[pos] = s;
    }
}

// ---------------- tensor-core GEMM (mma.sync m16n8k16 fp16 -> fp32) ----------
// Optional epilogue scale: C[row,:] *= g_dis[row]  (folds GCN norm into features)
__device__ __forceinline__ uint4 cvt8(const float* p) {
    const float4* s = (const float4*)p;
    float4 f0 = s[0], f1 = s[1];
    uint4 v;
    *(__half2*)&v.x = __floats2half2_rn(f0.x, f0.y);
    *(__half2*)&v.y = __floats2half2_rn(f0.z, f0.w);
    *(__half2*)&v.z = __floats2half2_rn(f1.x, f1.y);
    *(__half2*)&v.w = __floats2half2_rn(f1.z, f1.w);
    return v;
}
__device__ __forceinline__ uint4 ld_chunk(const __half* A, long long row, int ch) {
    return ((const uint4*)A)[row * 16 + ch];
}
__device__ __forceinline__ uint4 ld_chunk(const float* A, long long row, int ch) {
    return cvt8(&A[row * 128 + ch * 8]);
}
__device__ __forceinline__ uint4 ld_wchunk(const __half* W, int c) {
    return ((const uint4*)W)[c];
}
__device__ __forceinline__ uint4 ld_wchunk(const float* W, int c) {
    return cvt8(&W[c * 8]);
}

template <int NOUT, bool SCALE, typename AT, typename WT>
__global__ void k_gemm_mma(const AT* __restrict__ A, const WT* __restrict__ W,
                           __half2* __restrict__ C, int M) {
    constexpr int K = 128;
    constexpr int AST = 136;
    constexpr int WST = NOUT + 8;
    extern __shared__ __half sm[];
    __half* As = sm;
    __half* Ws = sm + 128 * AST;
    int tid = threadIdx.x;
    int wid = tid >> 5, lane = tid & 31;
    int rb = blockIdx.x * 128;

    #pragma unroll
    for (int i = 0; i < 8; i++) {
        int c = tid + i * 256;
        int row = c >> 4, ch = c & 15;
        int gr = rb + row;
        uint4 v = make_uint4(0u, 0u, 0u, 0u);
        if (gr < M) v = ld_chunk(A, (long long)gr, ch);
        *(uint4*)&As[row * AST + ch * 8] = v;
    }
    {
        constexpr int NCH = K * NOUT / 8;
        #pragma unroll
        for (int c = tid; c < NCH; c += 256) {
            int row = c / (NOUT / 8), col = c % (NOUT / 8);
            *(uint4*)&Ws[row * WST + col * 8] = ld_wchunk(W, c);
        }
    }
    __syncthreads();

    constexpr int NT = NOUT / 8;
    float acc[NT][4];
    #pragma unroll
    for (int i = 0; i < NT; i++) {
        acc[i][0] = acc[i][1] = acc[i][2] = acc[i][3] = 0.f;
    }

    uint32_t a_base = (uint32_t)__cvta_generic_to_shared(
                          &As[(wid * 16 + (lane & 15)) * AST]) + ((lane >> 4) << 4);
    uint32_t b_base = (uint32_t)__cvta_generic_to_shared(
                          &Ws[(lane & 15) * WST]) + ((lane >> 4) << 4);

    #pragma unroll
    for (int kk = 0; kk < K / 16; kk++) {
        uint32_t a0, a1, a2, a3;
        asm volatile("ldmatrix.sync.aligned.m8n8.x4.shared.b16 {%0,%1,%2,%3}, [%4];"
                     : "=r"(a0), "=r"(a1), "=r"(a2), "=r"(a3)
                     : "r"(a_base + kk * 32));
        uint32_t brow = b_base + kk * 16 * (WST * 2);
        #pragma unroll
        for (int n2 = 0; n2 < NOUT / 16; n2++) {
            uint32_t b0, b1, b2, b3;
            asm volatile("ldmatrix.sync.aligned.m8n8.x4.trans.shared.b16 {%0,%1,%2,%3}, [%4];"
                         : "=r"(b0), "=r"(b1), "=r"(b2), "=r"(b3)
                         : "r"(brow + n2 * 32));
            asm volatile("mma.sync.aligned.m16n8k16.row.col.f32.f16.f16.f32 "
                         "{%0,%1,%2,%3}, {%4,%5,%6,%7}, {%8,%9}, {%0,%1,%2,%3};"
                         : "+f"(acc[2*n2][0]), "+f"(acc[2*n2][1]),
                           "+f"(acc[2*n2][2]), "+f"(acc[2*n2][3])
                         : "r"(a0), "r"(a1), "r"(a2), "r"(a3), "r"(b0), "r"(b1));
            asm volatile("mma.sync.aligned.m16n8k16.row.col.f32.f16.f16.f32 "
                         "{%0,%1,%2,%3}, {%4,%5,%6,%7}, {%8,%9}, {%0,%1,%2,%3};"
                         : "+f"(acc[2*n2+1][0]), "+f"(acc[2*n2+1][1]),
                           "+f"(acc[2*n2+1][2]), "+f"(acc[2*n2+1][3])
                         : "r"(a0), "r"(a1), "r"(a2), "r"(a3), "r"(b2), "r"(b3));
        }
    }

    int r0 = rb + wid * 16 + (lane >> 2);
    int cq = lane & 3;
    bool w0 = r0 < M, w1 = (r0 + 8) < M;
    float sc0 = 1.f, sc1 = 1.f;
    if (SCALE) {
        if (w0) sc0 = g_dis[r0];
        if (w1) sc1 = g_dis[r0 + 8];
    }
    #pragma unroll
    for (int nt = 0; nt < NT; nt++) {
        if (w0) C[(long long)r0 * (NOUT/2) + nt * 4 + cq] =
                    __floats2half2_rn(acc[nt][0] * sc0, acc[nt][1] * sc0);
        if (w1) C[(long long)(r0 + 8) * (NOUT/2) + nt * 4 + cq] =
                    __floats2half2_rn(acc[nt][2] * sc1, acc[nt][3] * sc1);
    }
}

// ---------------- aggregation kernels (weight-free gathers) --------------------

__global__ void k_agg1(const float* __restrict__ b1) {
    int gw   = (blockIdx.x * blockDim.x + threadIdx.x) >> 5;
    int lane = threadIdx.x & 31;
    if (gw >= NN) return;
    int d = gw;
    int s0 = g_rowptr[d], s1 = g_rowptr[d + 1];
    float4 acc = make_float4(0.f, 0.f, 0.f, 0.f);
    for (int j0 = s0; j0 < s1; j0 += 32) {
        int jj = j0 + lane;
        int s_l = (jj < s1) ? g_csr_src[jj] : 0;
        int m = min(32, s1 - j0);
        for (int k = 0; k < m; k++) {
            int s = __shfl_sync(0xffffffffu, s_l, k);
            uint2 raw = g_h1h[s * 32 + lane];
            float2 fa = __half22float2(*(__half2*)&raw.x);
            float2 fb = __half22float2(*(__half2*)&raw.y);
            acc.x += fa.x; acc.y += fa.y;
            acc.z += fb.x; acc.w += fb.y;
        }
    }
    float dd = g_dis[d];
    uint2 hraw = g_h1h[d * 32 + lane];              // self row (already *dis)
    float2 ha = __half22float2(*(__half2*)&hraw.x);
    float2 hb = __half22float2(*(__half2*)&hraw.y);
    float4 bv = ((const float4*)b1)[lane];
    float ox = fmaxf(dd * (acc.x + ha.x) + bv.x, 0.f);
    float oy = fmaxf(dd * (acc.y + ha.y) + bv.y, 0.f);
    float oz = fmaxf(dd * (acc.z + hb.x) + bv.z, 0.f);
    float ow = fmaxf(dd * (acc.w + hb.y) + bv.w, 0.f);
    uint2 o;
    *(__half2*)&o.x = __floats2half2_rn(ox, oy);
    *(__half2*)&o.y = __floats2half2_rn(oz, ow);
    g_r1h[d * 32 + lane] = o;
}

__global__ void k_agg2_pool(const float* __restrict__ b2,
                            const void* __restrict__ batch) {
    int gw   = (blockIdx.x * blockDim.x + threadIdx.x) >> 5;
    int lane = threadIdx.x & 31;
    if (gw >= NN) return;
    int is64 = g_is64;
    int d = gw;
    int s0 = g_rowptr[d], s1 = g_rowptr[d + 1];
    float2 acc = make_float2(0.f, 0.f);
    for (int j0 = s0; j0 < s1; j0 += 32) {
        int jj = j0 + lane;
        int s_l = (jj < s1) ? g_csr_src[jj] : 0;
        int m = min(32, s1 - j0);
        for (int k = 0; k < m; k++) {
            int s = __shfl_sync(0xffffffffu, s_l, k);
            unsigned raw = g_h2h[s * 32 + lane];
            float2 v = __half22float2(*(__half2*)&raw);
            acc.x += v.x; acc.y += v.y;
        }
    }
    float dd = g_dis[d];
    unsigned hraw = g_h2h[d * 32 + lane];           // self row (already *dis)
    float2 hv = __half22float2(*(__half2*)&hraw);
    float2 bv = ((const float2*)b2)[lane];
    float ox = dd * (acc.x + hv.x) + bv.x;
    float oy = dd * (acc.y + hv.y) + bv.y;
    int g = ld_idx(batch, d, is64);
    atomicAdd(&g_pool[g * NH2 + lane * 2 + 0], ox);
    atomicAdd(&g_pool[g * NH2 + lane * 2 + 1], oy);
    if (lane == 0) atomicAdd(&g_pcnt[g], 1.0f);
}

__global__ void k_final(const float* __restrict__ Wfc,
                        const float* __restrict__ bfc,
                        float* __restrict__ out) {
    int g = blockIdx.x;
    int c = threadIdx.x;
    if (c >= NC) return;
    float inv = 1.0f / fmaxf(g_pcnt[g], 1.0f);
    float s = 0.f;
    #pragma unroll 8
    for (int f = 0; f < NH2; f++) {
        s += g_pool[g * NH2 + f] * Wfc[f * NC + c];
    }
    out[g * NC + c] = s * inv + bfc[c];
}

// ---------------- launch -----------------------------------------------------

extern "C" void kernel_launch(void* const* d_in, const int* in_sizes, int n_in,
                              void* d_out, int out_size) {
    const float* x     = (const float*)d_in[0];
    const void*  ei    = d_in[1];
    const void*  batch = d_in[2];
    const float* W1    = (const float*)d_in[3];
    const float* b1    = (const float*)d_in[4];
    const float* W2    = (const float*)d_in[5];
    const float* b2    = (const float*)d_in[6];
    const float* Wfc   = (const float*)d_in[7];
    const float* bfc   = (const float*)d_in[8];
    float* out = (float*)d_out;

    const int TB = 256;
    const int GB = (NN + 127) / 128;
    const int SM1 = (128 * 136 + 128 * 136) * 2;  // 69632 B
    const int SM2 = (128 * 136 + 128 * 72) * 2;   // 53248 B
    cudaFuncSetAttribute((const void*)k_gemm_mma<NH1, true, float, float>,
                         cudaFuncAttributeMaxDynamicSharedMemorySize, SM1);
    cudaFuncSetAttribute((const void*)k_gemm_mma<NH2, true, __half, float>,
                         cudaFuncAttributeMaxDynamicSharedMemorySize, SM2);

    // side stream + fork/join events (created on first, uncaptured, call;
    // no device memory involved)
    static cudaStream_t s2 = nullptr;
    static cudaEvent_t evF = nullptr, evJ = nullptr;
    if (s2 == nullptr) {
        cudaStreamCreateWithFlags(&s2, cudaStreamNonBlocking);
        cudaEventCreateWithFlags(&evF, cudaEventDisableTiming);
        cudaEventCreateWithFlags(&evJ, cudaEventDisableTiming);
    }

    // 0: histogram (+ dtype detect)
    k_hist<<<(NE + TB - 1) / TB, TB>>>(ei);
    // 1: single-pass scan (dis + woff ready after this)
    k_scan<<<SCAN_NB, SCAN_B>>>();

    // fork: GEMM1 runs on s2 concurrently with scatter on the main stream
    cudaEventRecord(evF, 0);
    cudaStreamWaitEvent(s2, evF, 0);
    {
        __half2* h1p; cudaGetSymbolAddress((void**)&h1p, g_h1h);
        k_gemm_mma<NH1, true, float, float><<<GB, 256, SM1, s2>>>(x, W1, h1p, NN);
    }
    // 2: scatter on main stream (concurrent with GEMM1)
    k_scatter<<<(NE + TB - 1) / TB, TB>>>(ei);
    // join: main stream waits for GEMM1
    cudaEventRecord(evJ, s2);
    cudaStreamWaitEvent(0, evJ, 0);

    // 3: agg1 + bias + relu -> r1h (needs csr + h1h)
    k_agg1<<<(NN * 32 + TB - 1) / TB, TB>>>(b1);
    // 4: GEMM2 with dis epilogue
    {
        __half* r1p;  cudaGetSymbolAddress((void**)&r1p, g_r1h);
        __half2* h2p; cudaGetSymbolAddress((void**)&h2p, g_h2h);
        k_gemm_mma<NH2, true, __half, float><<<GB, 256, SM2>>>(r1p, W2, h2p, NN);
    }
    // 5: agg2 fused with pooling
    k_agg2_pool<<<(NN * 32 + TB - 1) / TB, TB>>>(b2, batch);
    // 6: final FC
    k_final<<<NG, 32>>>(Wfc, bfc, out);
}

// round 14
// speedup vs baseline: 1.0270x; 1.0270x over previous
#include <cuda_runtime.h>
#include <cuda_fp16.h>
#include <cstdint>

// Problem constants (fixed by the dataset)
#define NN 100000        // nodes
#define NE 3200000       // edges
#define DF 128           // input feat
#define NH1 128          // layer1 out
#define NH2 64           // layer2 out
#define NG 256           // graphs
#define NC 10            // classes

#define SCAN_B 1024
#define SCAN_NB ((NN + SCAN_B - 1) / SCAN_B)   // 98
#define SS_THREADS (SCAN_NB * SCAN_B)          // 100352

// ---------------- scratch (static device memory; no allocation) -------------
// Invariants across calls (zero-init at load, re-established every call):
//   g_cnt == 0, g_blocksum == 0, g_arrive == 0, g_depart == 0
__device__ int   g_is64;               // 1 if indices are int64, 0 if int32
__device__ float g_dis[NN];            // deg^-1/2
__device__ int   g_cnt[NN];            // per-dst edge count
__device__ int   g_rowptr[NN + 1];     // CSR row pointers
__device__ int   g_woff[NN];           // scatter write offsets
__device__ int   g_blocksum[SCAN_NB];  // flagged block sums (value+1)
__device__ int   g_arrive, g_depart;   // in-kernel global barrier counters
__device__ int   g_csr_src[NE];        // CSR column (src) indices
__device__ __align__(16) uint2 g_h1h[NN * 32];    // (x @ W1)*dis, fp16, 128 h/row
__device__ __align__(16) uint2 g_r1h[NN * 32];    // relu(gcn1), fp16
__device__ __align__(16) unsigned g_h2h[NN * 32]; // (r1 @ W2)*dis, fp16, 64 h/row
__device__ float g_pool[NG * NH2];     // graph sums
__device__ float g_pcnt[NG];           // graph node counts

// index load helper: p holds either int32 or int64 elements
__device__ __forceinline__ int ld_idx(const void* p, long long i, int is64) {
    if (is64) return (int)((const long long*)p)[i];
    return ((const int*)p)[i];
}

// ---------------- hist (+ dtype detect) ----------------------------------------

__global__ void k_hist(const void* __restrict__ ei) {
    __shared__ int nz;
    if (threadIdx.x == 0) nz = 0;
    __syncthreads();
    if (threadIdx.x < 256) {
        if (((const int*)ei)[2 * threadIdx.x + 1] != 0) atomicOr(&nz, 1);
    }
    __syncthreads();
    int is64 = (nz == 0);
    if (blockIdx.x == 0 && threadIdx.x == 0) g_is64 = is64;
    int e = blockIdx.x * blockDim.x + threadIdx.x;
    if (e < NE) {
        int d = ld_idx(ei, (long long)NE + e, is64);
        atomicAdd(&g_cnt[d], 1);
    }
}

// ---------------- fused scan + scatter ------------------------------------------
// Phase 1: single-pass exclusive scan of g_cnt (decoupled lookback), dis, woff.
// Global barrier (98 co-resident blocks). Phase 2: CSR scatter, strided.
__global__ void k_scan_scatter(const void* __restrict__ ei) {
    __shared__ int s[SCAN_B];
    __shared__ int pre[SCAN_NB];
    int t = threadIdx.x, b = blockIdx.x;
    int i = b * SCAN_B + t;
    int v = 0;
    if (i < NN) {
        v = g_cnt[i];
        g_cnt[i] = 0;                       // re-establish invariant for next call
        g_dis[i] = rsqrtf((float)v + 1.0f);
    }
    s[t] = v;
    __syncthreads();
    #pragma unroll
    for (int off = 1; off < SCAN_B; off <<= 1) {
        int add = (t >= off) ? s[t - off] : 0;
        __syncthreads();
        s[t] += add;
        __syncthreads();
    }
    int incl = s[t];
    if (t == SCAN_B - 1) {
        __threadfence();
        atomicExch(&g_blocksum[b], incl + 1);
    }
    if (b == 0) {
        for (int j = t; j < NG * NH2; j += SCAN_B) g_pool[j] = 0.f;
        if (t < NG) g_pcnt[t] = 0.f;
    }
    if (t < b) {
        volatile int* bs = g_blocksum;
        int x;
        do { x = bs[t]; } while (x == 0);
        pre[t] = x - 1;
    }
    __syncthreads();
    __shared__ int prefix;
    if (t == 0) {
        int p = 0;
        for (int j = 0; j < b; j++) p += pre[j];
        prefix = p;
    }
    __syncthreads();
    if (i < NN) {
        int excl = prefix + incl - v;
        g_rowptr[i] = excl;
        g_woff[i] = excl;
    }
    if (i == 0) g_rowptr[NN] = NE;

    // ---- global barrier: all woff writes visible before any scatter ----
    __threadfence();
    __syncthreads();
    if (t == 0) {
        atomicAdd(&g_arrive, 1);
        volatile int* ar = &g_arrive;
        while (*ar < SCAN_NB) { }
    }
    __syncthreads();

    // blocksum consumed by all lookbacks -> safe to re-zero for next call
    if (b == 0 && t < SCAN_NB) g_blocksum[t] = 0;

    // ---- phase 2: scatter (strided, coalesced index reads) ----
    int is64 = g_is64;
    for (long long e = b * SCAN_B + t; e < NE; e += SS_THREADS) {
        int sidx = ld_idx(ei, e, is64);
        int d    = ld_idx(ei, (long long)NE + e, is64);
        int pos = atomicAdd(&g_woff[d], 1);
        g_csr_src[pos] = sidx;
    }

    // ---- departure: last block resets barrier counters ----
    __threadfence();
    __syncthreads();
    if (t == 0) {
        int d = atomicAdd(&g_depart, 1);
        if (d == SCAN_NB - 1) {
            g_arrive = 0;
            g_depart = 0;
            __threadfence();
        }
    }
}

// ---------------- tensor-core GEMM (mma.sync m16n8k16 fp16 -> fp32) ----------
// Optional epilogue scale: C[row,:] *= g_dis[row]  (folds GCN norm into features)
__device__ __forceinline__ uint4 cvt8(const float* p) {
    const float4* s = (const float4*)p;
    float4 f0 = s[0], f1 = s[1];
    uint4 v;
    *(__half2*)&v.x = __floats2half2_rn(f0.x, f0.y);
    *(__half2*)&v.y = __floats2half2_rn(f0.z, f0.w);
    *(__half2*)&v.z = __floats2half2_rn(f1.x, f1.y);
    *(__half2*)&v.w = __floats2half2_rn(f1.z, f1.w);
    return v;
}
__device__ __forceinline__ uint4 ld_chunk(const __half* A, long long row, int ch) {
    return ((const uint4*)A)[row * 16 + ch];
}
__device__ __forceinline__ uint4 ld_chunk(const float* A, long long row, int ch) {
    return cvt8(&A[row * 128 + ch * 8]);
}
__device__ __forceinline__ uint4 ld_wchunk(const __half* W, int c) {
    return ((const uint4*)W)[c];
}
__device__ __forceinline__ uint4 ld_wchunk(const float* W, int c) {
    return cvt8(&W[c * 8]);
}

template <int NOUT, bool SCALE, typename AT, typename WT>
__global__ void k_gemm_mma(const AT* __restrict__ A, const WT* __restrict__ W,
                           __half2* __restrict__ C, int M) {
    constexpr int K = 128;
    constexpr int AST = 136;
    constexpr int WST = NOUT + 8;
    extern __shared__ __half sm[];
    __half* As = sm;
    __half* Ws = sm + 128 * AST;
    int tid = threadIdx.x;
    int wid = tid >> 5, lane = tid & 31;
    int rb = blockIdx.x * 128;

    #pragma unroll
    for (int i = 0; i < 8; i++) {
        int c = tid + i * 256;
        int row = c >> 4, ch = c & 15;
        int gr = rb + row;
        uint4 v = make_uint4(0u, 0u, 0u, 0u);
        if (gr < M) v = ld_chunk(A, (long long)gr, ch);
        *(uint4*)&As[row * AST + ch * 8] = v;
    }
    {
        constexpr int NCH = K * NOUT / 8;
        #pragma unroll
        for (int c = tid; c < NCH; c += 256) {
            int row = c / (NOUT / 8), col = c % (NOUT / 8);
            *(uint4*)&Ws[row * WST + col * 8] = ld_wchunk(W, c);
        }
    }
    __syncthreads();

    constexpr int NT = NOUT / 8;
    float acc[NT][4];
    #pragma unroll
    for (int i = 0; i < NT; i++) {
        acc[i][0] = acc[i][1] = acc[i][2] = acc[i][3] = 0.f;
    }

    uint32_t a_base = (uint32_t)__cvta_generic_to_shared(
                          &As[(wid * 16 + (lane & 15)) * AST]) + ((lane >> 4) << 4);
    uint32_t b_base = (uint32_t)__cvta_generic_to_shared(
                          &Ws[(lane & 15) * WST]) + ((lane >> 4) << 4);

    #pragma unroll
    for (int kk = 0; kk < K / 16; kk++) {
        uint32_t a0, a1, a2, a3;
        asm volatile("ldmatrix.sync.aligned.m8n8.x4.shared.b16 {%0,%1,%2,%3}, [%4];"
                     : "=r"(a0), "=r"(a1), "=r"(a2), "=r"(a3)
                     : "r"(a_base + kk * 32));
        uint32_t brow = b_base + kk * 16 * (WST * 2);
        #pragma unroll
        for (int n2 = 0; n2 < NOUT / 16; n2++) {
            uint32_t b0, b1, b2, b3;
            asm volatile("ldmatrix.sync.aligned.m8n8.x4.trans.shared.b16 {%0,%1,%2,%3}, [%4];"
                         : "=r"(b0), "=r"(b1), "=r"(b2), "=r"(b3)
                         : "r"(brow + n2 * 32));
            asm volatile("mma.sync.aligned.m16n8k16.row.col.f32.f16.f16.f32 "
                         "{%0,%1,%2,%3}, {%4,%5,%6,%7}, {%8,%9}, {%0,%1,%2,%3};"
                         : "+f"(acc[2*n2][0]), "+f"(acc[2*n2][1]),
                           "+f"(acc[2*n2][2]), "+f"(acc[2*n2][3])
                         : "r"(a0), "r"(a1), "r"(a2), "r"(a3), "r"(b0), "r"(b1));
            asm volatile("mma.sync.aligned.m16n8k16.row.col.f32.f16.f16.f32 "
                         "{%0,%1,%2,%3}, {%4,%5,%6,%7}, {%8,%9}, {%0,%1,%2,%3};"
                         : "+f"(acc[2*n2+1][0]), "+f"(acc[2*n2+1][1]),
                           "+f"(acc[2*n2+1][2]), "+f"(acc[2*n2+1][3])
                         : "r"(a0), "r"(a1), "r"(a2), "r"(a3), "r"(b2), "r"(b3));
        }
    }

    int r0 = rb + wid * 16 + (lane >> 2);
    int cq = lane & 3;
    bool w0 = r0 < M, w1 = (r0 + 8) < M;
    float sc0 = 1.f, sc1 = 1.f;
    if (SCALE) {
        if (w0) sc0 = g_dis[r0];
        if (w1) sc1 = g_dis[r0 + 8];
    }
    #pragma unroll
    for (int nt = 0; nt < NT; nt++) {
        if (w0) C[(long long)r0 * (NOUT/2) + nt * 4 + cq] =
                    __floats2half2_rn(acc[nt][0] * sc0, acc[nt][1] * sc0);
        if (w1) C[(long long)(r0 + 8) * (NOUT/2) + nt * 4 + cq] =
                    __floats2half2_rn(acc[nt][2] * sc1, acc[nt][3] * sc1);
    }
}

// ---------------- aggregation kernels (weight-free gathers) --------------------

__global__ void k_agg1(const float* __restrict__ b1) {
    int gw   = (blockIdx.x * blockDim.x + threadIdx.x) >> 5;
    int lane = threadIdx.x & 31;
    if (gw >= NN) return;
    int d = gw;
    int s0 = g_rowptr[d], s1 = g_rowptr[d + 1];
    float4 acc = make_float4(0.f, 0.f, 0.f, 0.f);
    for (int j0 = s0; j0 < s1; j0 += 32) {
        int jj = j0 + lane;
        int s_l = (jj < s1) ? g_csr_src[jj] : 0;
        int m = min(32, s1 - j0);
        for (int k = 0; k < m; k++) {
            int s = __shfl_sync(0xffffffffu, s_l, k);
            uint2 raw = g_h1h[s * 32 + lane];
            float2 fa = __half22float2(*(__half2*)&raw.x);
            float2 fb = __half22float2(*(__half2*)&raw.y);
            acc.x += fa.x; acc.y += fa.y;
            acc.z += fb.x; acc.w += fb.y;
        }
    }
    float dd = g_dis[d];
    uint2 hraw = g_h1h[d * 32 + lane];              // self row (already *dis)
    float2 ha = __half22float2(*(__half2*)&hraw.x);
    float2 hb = __half22float2(*(__half2*)&hraw.y);
    float4 bv = ((const float4*)b1)[lane];
    float ox = fmaxf(dd * (acc.x + ha.x) + bv.x, 0.f);
    float oy = fmaxf(dd * (acc.y + ha.y) + bv.y, 0.f);
    float oz = fmaxf(dd * (acc.z + hb.x) + bv.z, 0.f);
    float ow = fmaxf(dd * (acc.w + hb.y) + bv.w, 0.f);
    uint2 o;
    *(__half2*)&o.x = __floats2half2_rn(ox, oy);
    *(__half2*)&o.y = __floats2half2_rn(oz, ow);
    g_r1h[d * 32 + lane] = o;
}

__global__ void k_agg2_pool(const float* __restrict__ b2,
                            const void* __restrict__ batch) {
    int gw   = (blockIdx.x * blockDim.x + threadIdx.x) >> 5;
    int lane = threadIdx.x & 31;
    if (gw >= NN) return;
    int is64 = g_is64;
    int d = gw;
    int s0 = g_rowptr[d], s1 = g_rowptr[d + 1];
    float2 acc = make_float2(0.f, 0.f);
    for (int j0 = s0; j0 < s1; j0 += 32) {
        int jj = j0 + lane;
        int s_l = (jj < s1) ? g_csr_src[jj] : 0;
        int m = min(32, s1 - j0);
        for (int k = 0; k < m; k++) {
            int s = __shfl_sync(0xffffffffu, s_l, k);
            unsigned raw = g_h2h[s * 32 + lane];
            float2 v = __half22float2(*(__half2*)&raw);
            acc.x += v.x; acc.y += v.y;
        }
    }
    float dd = g_dis[d];
    unsigned hraw = g_h2h[d * 32 + lane];           // self row (already *dis)
    float2 hv = __half22float2(*(__half2*)&hraw);
    float2 bv = ((const float2*)b2)[lane];
    float ox = dd * (acc.x + hv.x) + bv.x;
    float oy = dd * (acc.y + hv.y) + bv.y;
    int g = ld_idx(batch, d, is64);
    atomicAdd(&g_pool[g * NH2 + lane * 2 + 0], ox);
    atomicAdd(&g_pool[g * NH2 + lane * 2 + 1], oy);
    if (lane == 0) atomicAdd(&g_pcnt[g], 1.0f);
}

__global__ void k_final(const float* __restrict__ Wfc,
                        const float* __restrict__ bfc,
                        float* __restrict__ out) {
    int g = blockIdx.x;
    int c = threadIdx.x;
    if (c >= NC) return;
    float inv = 1.0f / fmaxf(g_pcnt[g], 1.0f);
    float s = 0.f;
    #pragma unroll 8
    for (int f = 0; f < NH2; f++) {
        s += g_pool[g * NH2 + f] * Wfc[f * NC + c];
    }
    out[g * NC + c] = s * inv + bfc[c];
}

// ---------------- launch -----------------------------------------------------

extern "C" void kernel_launch(void* const* d_in, const int* in_sizes, int n_in,
                              void* d_out, int out_size) {
    const float* x     = (const float*)d_in[0];
    const void*  ei    = d_in[1];
    const void*  batch = d_in[2];
    const float* W1    = (const float*)d_in[3];
    const float* b1    = (const float*)d_in[4];
    const float* W2    = (const float*)d_in[5];
    const float* b2    = (const float*)d_in[6];
    const float* Wfc   = (const float*)d_in[7];
    const float* bfc   = (const float*)d_in[8];
    float* out = (float*)d_out;

    const int TB = 256;
    const int GB = (NN + 127) / 128;
    const int SM1 = (128 * 136 + 128 * 136) * 2;  // 69632 B
    const int SM2 = (128 * 136 + 128 * 72) * 2;   // 53248 B
    cudaFuncSetAttribute((const void*)k_gemm_mma<NH1, true, float, float>,
                         cudaFuncAttributeMaxDynamicSharedMemorySize, SM1);
    cudaFuncSetAttribute((const void*)k_gemm_mma<NH2, true, __half, float>,
                         cudaFuncAttributeMaxDynamicSharedMemorySize, SM2);

    // 0: histogram (+ dtype detect)
    k_hist<<<(NE + TB - 1) / TB, TB>>>(ei);
    // 1: fused scan + scatter (co-resident; in-kernel global barrier)
    k_scan_scatter<<<SCAN_NB, SCAN_B>>>(ei);
    // 2: GEMM1 with dis epilogue: h1h = half(dis * (x @ half(W1)))
    {
        __half2* h1p; cudaGetSymbolAddress((void**)&h1p, g_h1h);
        k_gemm_mma<NH1, true, float, float><<<GB, 256, SM1>>>(x, W1, h1p, NN);
    }
    // 3: agg1  <-- ncu capture slot
    k_agg1<<<(NN * 32 + TB - 1) / TB, TB>>>(b1);
    // 4: GEMM2 with dis epilogue
    {
        __half* r1p;  cudaGetSymbolAddress((void**)&r1p, g_r1h);
        __half2* h2p; cudaGetSymbolAddress((void**)&h2p, g_h2h);
        k_gemm_mma<NH2, true, __half, float><<<GB, 256, SM2>>>(r1p, W2, h2p, NN);
    }
    // 5: agg2 fused with pooling
    k_agg2_pool<<<(NN * 32 + TB - 1) / TB, TB>>>(b2, batch);
    // 6: final FC
    k_final<<<NG, 32>>>(Wfc, bfc, out);
}

// round 15
// speedup vs baseline: 1.0550x; 1.0273x over previous
#include <cuda_runtime.h>
#include <cuda_fp16.h>
#include <cstdint>

// Problem constants (fixed by the dataset)
#define NN 100000        // nodes
#define NE 3200000       // edges
#define DF 128           // input feat
#define NH1 128          // layer1 out
#define NH2 64           // layer2 out
#define NG 256           // graphs
#define NC 10            // classes

#define SCAN_B 1024
#define SCAN_NB ((NN + SCAN_B - 1) / SCAN_B)   // 98

// ---------------- scratch (static device memory; no allocation) -------------
// Invariants across calls: g_cnt == 0 on entry; g_blocksum == 0 on entry.
__device__ int   g_is64;               // 1 if indices are int64, 0 if int32
__device__ float g_dis[NN];            // deg^-1/2
__device__ int   g_cnt[NN];            // per-dst edge count
__device__ int   g_rowptr[NN + 1];     // CSR row pointers
__device__ int   g_woff[NN];           // scatter write offsets
__device__ int   g_blocksum[SCAN_NB];  // flagged block sums (value+1)
__device__ int   g_csr_src[NE];        // CSR column (src) indices
__device__ __align__(16) uint2 g_h1h[NN * 32];    // (x @ W1)*dis, fp16, 128 h/row
__device__ __align__(16) uint2 g_r1h[NN * 32];    // relu(gcn1), fp16
__device__ __align__(16) unsigned g_h2h[NN * 32]; // (r1 @ W2)*dis, fp16, 64 h/row
__device__ float g_pool[NG * NH2];     // graph sums
__device__ float g_pcnt[NG];           // graph node counts

// index load helper: p holds either int32 or int64 elements
__device__ __forceinline__ int ld_idx(const void* p, long long i, int is64) {
    if (is64) return (int)((const long long*)p)[i];
    return ((const int*)p)[i];
}

// ---------------- hist (+ dtype detect) ----------------------------------------

__global__ void k_hist(const void* __restrict__ ei) {
    __shared__ int nz;
    if (threadIdx.x == 0) nz = 0;
    __syncthreads();
    if (threadIdx.x < 256) {
        if (((const int*)ei)[2 * threadIdx.x + 1] != 0) atomicOr(&nz, 1);
    }
    __syncthreads();
    int is64 = (nz == 0);
    if (blockIdx.x == 0 && threadIdx.x == 0) g_is64 = is64;
    int e = blockIdx.x * blockDim.x + threadIdx.x;
    if (e < NE) {
        int d = ld_idx(ei, (long long)NE + e, is64);
        atomicAdd(&g_cnt[d], 1);
    }
}

// ---------------- single-pass scan (decoupled lookback) ------------------------
__global__ void k_scan() {
    __shared__ int s[SCAN_B];
    __shared__ int pre[SCAN_NB];
    int t = threadIdx.x, b = blockIdx.x;
    int i = b * SCAN_B + t;
    int v = 0;
    if (i < NN) {
        v = g_cnt[i];
        g_cnt[i] = 0;                       // re-establish invariant for next call
        g_dis[i] = rsqrtf((float)v + 1.0f);
    }
    s[t] = v;
    __syncthreads();
    #pragma unroll
    for (int off = 1; off < SCAN_B; off <<= 1) {
        int add = (t >= off) ? s[t - off] : 0;
        __syncthreads();
        s[t] += add;
        __syncthreads();
    }
    int incl = s[t];
    if (t == SCAN_B - 1) {
        __threadfence();
        atomicExch(&g_blocksum[b], incl + 1);
    }
    if (b == 0) {
        for (int j = t; j < NG * NH2; j += SCAN_B) g_pool[j] = 0.f;
        if (t < NG) g_pcnt[t] = 0.f;
    }
    if (t < b) {
        volatile int* bs = g_blocksum;
        int x;
        do { x = bs[t]; } while (x == 0);
        pre[t] = x - 1;
    }
    __syncthreads();
    __shared__ int prefix;
    if (t == 0) {
        int p = 0;
        for (int j = 0; j < b; j++) p += pre[j];
        prefix = p;
    }
    __syncthreads();
    if (i < NN) {
        int excl = prefix + incl - v;
        g_rowptr[i] = excl;
        g_woff[i] = excl;
    }
    if (i == 0) g_rowptr[NN] = NE;
}

// ---------------- scatter -------------------------------------------------------

__global__ void k_scatter(const void* __restrict__ ei) {
    if (blockIdx.x == 0 && threadIdx.x < SCAN_NB) g_blocksum[threadIdx.x] = 0;
    int e = blockIdx.x * blockDim.x + threadIdx.x;
    int is64 = g_is64;
    if (e < NE) {
        int s = ld_idx(ei, e, is64);
        int d = ld_idx(ei, (long long)NE + e, is64);
        int pos = atomicAdd(&g_woff[d], 1);
        g_csr_src[pos] = s;
    }
}

// ---------------- tensor-core GEMM (mma.sync m16n8k16 fp16 -> fp32) ----------
// Optional epilogue scale: C[row,:] *= g_dis[row]  (folds GCN norm into features)
__device__ __forceinline__ uint4 cvt8(const float* p) {
    const float4* s = (const float4*)p;
    float4 f0 = s[0], f1 = s[1];
    uint4 v;
    *(__half2*)&v.x = __floats2half2_rn(f0.x, f0.y);
    *(__half2*)&v.y = __floats2half2_rn(f0.z, f0.w);
    *(__half2*)&v.z = __floats2half2_rn(f1.x, f1.y);
    *(__half2*)&v.w = __floats2half2_rn(f1.z, f1.w);
    return v;
}
__device__ __forceinline__ uint4 ld_chunk(const __half* A, long long row, int ch) {
    return ((const uint4*)A)[row * 16 + ch];
}
__device__ __forceinline__ uint4 ld_chunk(const float* A, long long row, int ch) {
    return cvt8(&A[row * 128 + ch * 8]);
}
__device__ __forceinline__ uint4 ld_wchunk(const __half* W, int c) {
    return ((const uint4*)W)[c];
}
__device__ __forceinline__ uint4 ld_wchunk(const float* W, int c) {
    return cvt8(&W[c * 8]);
}

template <int NOUT, bool SCALE, typename AT, typename WT>
__global__ void k_gemm_mma(const AT* __restrict__ A, const WT* __restrict__ W,
                           __half2* __restrict__ C, int M) {
    constexpr int K = 128;
    constexpr int AST = 136;
    constexpr int WST = NOUT + 8;
    extern __shared__ __half sm[];
    __half* As = sm;
    __half* Ws = sm + 128 * AST;
    int tid = threadIdx.x;
    int wid = tid >> 5, lane = tid & 31;
    int rb = blockIdx.x * 128;

    #pragma unroll
    for (int i = 0; i < 8; i++) {
        int c = tid + i * 256;
        int row = c >> 4, ch = c & 15;
        int gr = rb + row;
        uint4 v = make_uint4(0u, 0u, 0u, 0u);
        if (gr < M) v = ld_chunk(A, (long long)gr, ch);
        *(uint4*)&As[row * AST + ch * 8] = v;
    }
    {
        constexpr int NCH = K * NOUT / 8;
        #pragma unroll
        for (int c = tid; c < NCH; c += 256) {
            int row = c / (NOUT / 8), col = c % (NOUT / 8);
            *(uint4*)&Ws[row * WST + col * 8] = ld_wchunk(W, c);
        }
    }
    __syncthreads();

    constexpr int NT = NOUT / 8;
    float acc[NT][4];
    #pragma unroll
    for (int i = 0; i < NT; i++) {
        acc[i][0] = acc[i][1] = acc[i][2] = acc[i][3] = 0.f;
    }

    uint32_t a_base = (uint32_t)__cvta_generic_to_shared(
                          &As[(wid * 16 + (lane & 15)) * AST]) + ((lane >> 4) << 4);
    uint32_t b_base = (uint32_t)__cvta_generic_to_shared(
                          &Ws[(lane & 15) * WST]) + ((lane >> 4) << 4);

    #pragma unroll
    for (int kk = 0; kk < K / 16; kk++) {
        uint32_t a0, a1, a2, a3;
        asm volatile("ldmatrix.sync.aligned.m8n8.x4.shared.b16 {%0,%1,%2,%3}, [%4];"
                     : "=r"(a0), "=r"(a1), "=r"(a2), "=r"(a3)
                     : "r"(a_base + kk * 32));
        uint32_t brow = b_base + kk * 16 * (WST * 2);
        #pragma unroll
        for (int n2 = 0; n2 < NOUT / 16; n2++) {
            uint32_t b0, b1, b2, b3;
            asm volatile("ldmatrix.sync.aligned.m8n8.x4.trans.shared.b16 {%0,%1,%2,%3}, [%4];"
                         : "=r"(b0), "=r"(b1), "=r"(b2), "=r"(b3)
                         : "r"(brow + n2 * 32));
            asm volatile("mma.sync.aligned.m16n8k16.row.col.f32.f16.f16.f32 "
                         "{%0,%1,%2,%3}, {%4,%5,%6,%7}, {%8,%9}, {%0,%1,%2,%3};"
                         : "+f"(acc[2*n2][0]), "+f"(acc[2*n2][1]),
                           "+f"(acc[2*n2][2]), "+f"(acc[2*n2][3])
                         : "r"(a0), "r"(a1), "r"(a2), "r"(a3), "r"(b0), "r"(b1));
            asm volatile("mma.sync.aligned.m16n8k16.row.col.f32.f16.f16.f32 "
                         "{%0,%1,%2,%3}, {%4,%5,%6,%7}, {%8,%9}, {%0,%1,%2,%3};"
                         : "+f"(acc[2*n2+1][0]), "+f"(acc[2*n2+1][1]),
                           "+f"(acc[2*n2+1][2]), "+f"(acc[2*n2+1][3])
                         : "r"(a0), "r"(a1), "r"(a2), "r"(a3), "r"(b2), "r"(b3));
        }
    }

    int r0 = rb + wid * 16 + (lane >> 2);
    int cq = lane & 3;
    bool w0 = r0 < M, w1 = (r0 + 8) < M;
    float sc0 = 1.f, sc1 = 1.f;
    if (SCALE) {
        if (w0) sc0 = g_dis[r0];
        if (w1) sc1 = g_dis[r0 + 8];
    }
    #pragma unroll
    for (int nt = 0; nt < NT; nt++) {
        if (w0) C[(long long)r0 * (NOUT/2) + nt * 4 + cq] =
                    __floats2half2_rn(acc[nt][0] * sc0, acc[nt][1] * sc0);
        if (w1) C[(long long)(r0 + 8) * (NOUT/2) + nt * 4 + cq] =
                    __floats2half2_rn(acc[nt][2] * sc1, acc[nt][3] * sc1);
    }
}

// ---------------- aggregation kernels ------------------------------------------
// Weight-free gathers + grouped fp16 accumulation: 8 edges accumulate in HADD2
// registers, then flush to fp32 (cuts per-edge F2F+FADD down to 2 HADD2).

__global__ void k_agg1(const float* __restrict__ b1) {
    int gw   = (blockIdx.x * blockDim.x + threadIdx.x) >> 5;
    int lane = threadIdx.x & 31;
    if (gw >= NN) return;
    int d = gw;
    int s0 = g_rowptr[d], s1 = g_rowptr[d + 1];
    float4 acc = make_float4(0.f, 0.f, 0.f, 0.f);
    const __half2 hz = __float2half2_rn(0.f);
    for (int j0 = s0; j0 < s1; j0 += 32) {
        int jj = j0 + lane;
        int s_l = (jj < s1) ? g_csr_src[jj] : 0;
        int m = min(32, s1 - j0);
        int k = 0;
        while (k < m) {
            int kend = min(k + 8, m);
            __half2 h0 = hz, h1 = hz;
            for (; k < kend; k++) {
                int s = __shfl_sync(0xffffffffu, s_l, k);
                uint2 raw = g_h1h[s * 32 + lane];
                h0 = __hadd2(h0, *(__half2*)&raw.x);
                h1 = __hadd2(h1, *(__half2*)&raw.y);
            }
            float2 f0 = __half22float2(h0);
            float2 f1 = __half22float2(h1);
            acc.x += f0.x; acc.y += f0.y;
            acc.z += f1.x; acc.w += f1.y;
        }
    }
    float dd = g_dis[d];
    uint2 hraw = g_h1h[d * 32 + lane];              // self row (already *dis)
    float2 ha = __half22float2(*(__half2*)&hraw.x);
    float2 hb = __half22float2(*(__half2*)&hraw.y);
    float4 bv = ((const float4*)b1)[lane];
    float ox = fmaxf(dd * (acc.x + ha.x) + bv.x, 0.f);
    float oy = fmaxf(dd * (acc.y + ha.y) + bv.y, 0.f);
    float oz = fmaxf(dd * (acc.z + hb.x) + bv.z, 0.f);
    float ow = fmaxf(dd * (acc.w + hb.y) + bv.w, 0.f);
    uint2 o;
    *(__half2*)&o.x = __floats2half2_rn(ox, oy);
    *(__half2*)&o.y = __floats2half2_rn(oz, ow);
    g_r1h[d * 32 + lane] = o;
}

__global__ void k_agg2_pool(const float* __restrict__ b2,
                            const void* __restrict__ batch) {
    int gw   = (blockIdx.x * blockDim.x + threadIdx.x) >> 5;
    int lane = threadIdx.x & 31;
    if (gw >= NN) return;
    int is64 = g_is64;
    int d = gw;
    int s0 = g_rowptr[d], s1 = g_rowptr[d + 1];
    float2 acc = make_float2(0.f, 0.f);
    const __half2 hz = __float2half2_rn(0.f);
    for (int j0 = s0; j0 < s1; j0 += 32) {
        int jj = j0 + lane;
        int s_l = (jj < s1) ? g_csr_src[jj] : 0;
        int m = min(32, s1 - j0);
        int k = 0;
        while (k < m) {
            int kend = min(k + 8, m);
            __half2 h0 = hz;
            for (; k < kend; k++) {
                int s = __shfl_sync(0xffffffffu, s_l, k);
                unsigned raw = g_h2h[s * 32 + lane];
                h0 = __hadd2(h0, *(__half2*)&raw);
            }
            float2 f0 = __half22float2(h0);
            acc.x += f0.x; acc.y += f0.y;
        }
    }
    float dd = g_dis[d];
    unsigned hraw = g_h2h[d * 32 + lane];           // self row (already *dis)
    float2 hv = __half22float2(*(__half2*)&hraw);
    float2 bv = ((const float2*)b2)[lane];
    float ox = dd * (acc.x + hv.x) + bv.x;
    float oy = dd * (acc.y + hv.y) + bv.y;
    int g = ld_idx(batch, d, is64);
    atomicAdd(&g_pool[g * NH2 + lane * 2 + 0], ox);
    atomicAdd(&g_pool[g * NH2 + lane * 2 + 1], oy);
    if (lane == 0) atomicAdd(&g_pcnt[g], 1.0f);
}

__global__ void k_final(const float* __restrict__ Wfc,
                        const float* __restrict__ bfc,
                        float* __restrict__ out) {
    int g = blockIdx.x;
    int c = threadIdx.x;
    if (c >= NC) return;
    float inv = 1.0f / fmaxf(g_pcnt[g], 1.0f);
    float s = 0.f;
    #pragma unroll 8
    for (int f = 0; f < NH2; f++) {
        s += g_pool[g * NH2 + f] * Wfc[f * NC + c];
    }
    out[g * NC + c] = s * inv + bfc[c];
}

// ---------------- launch -----------------------------------------------------

extern "C" void kernel_launch(void* const* d_in, const int* in_sizes, int n_in,
                              void* d_out, int out_size) {
    const float* x     = (const float*)d_in[0];
    const void*  ei    = d_in[1];
    const void*  batch = d_in[2];
    const float* W1    = (const float*)d_in[3];
    const float* b1    = (const float*)d_in[4];
    const float* W2    = (const float*)d_in[5];
    const float* b2    = (const float*)d_in[6];
    const float* Wfc   = (const float*)d_in[7];
    const float* bfc   = (const float*)d_in[8];
    float* out = (float*)d_out;

    const int TB = 256;
    const int GB = (NN + 127) / 128;
    const int SM1 = (128 * 136 + 128 * 136) * 2;  // 69632 B
    const int SM2 = (128 * 136 + 128 * 72) * 2;   // 53248 B
    cudaFuncSetAttribute((const void*)k_gemm_mma<NH1, true, float, float>,
                         cudaFuncAttributeMaxDynamicSharedMemorySize, SM1);
    cudaFuncSetAttribute((const void*)k_gemm_mma<NH2, true, __half, float>,
                         cudaFuncAttributeMaxDynamicSharedMemorySize, SM2);

    // 0: histogram (+ dtype detect)
    k_hist<<<(NE + TB - 1) / TB, TB>>>(ei);
    // 1: single-pass scan (dis + woff ready after this)
    k_scan<<<SCAN_NB, SCAN_B>>>();
    // 2: GEMM1 with dis epilogue: h1h = half(dis * (x @ half(W1)))
    {
        __half2* h1p; cudaGetSymbolAddress((void**)&h1p, g_h1h);
        k_gemm_mma<NH1, true, float, float><<<GB, 256, SM1>>>(x, W1, h1p, NN);
    }
    // 3: scatter  <-- ncu capture slot
    k_scatter<<<(NE + TB - 1) / TB, TB>>>(ei);
    // 4: agg1 + bias + relu -> r1h (grouped fp16 accumulation)
    k_agg1<<<(NN * 32 + TB - 1) / TB, TB>>>(b1);
    // 5: GEMM2 with dis epilogue
    {
        __half* r1p;  cudaGetSymbolAddress((void**)&r1p, g_r1h);
        __half2* h2p; cudaGetSymbolAddress((void**)&h2p, g_h2h);
        k_gemm_mma<NH2, true, __half, float><<<GB, 256, SM2>>>(r1p, W2, h2p, NN);
    }
    // 6: agg2 fused with pooling (grouped fp16 accumulation)
    k_agg2_pool<<<(NN * 32 + TB - 1) / TB, TB>>>(b2, batch);
    // 7: final FC
    k_final<<<NG, 32>>>(Wfc, bfc, out);
}